// round 3
// baseline (speedup 1.0000x reference)
#include <cuda_runtime.h>
#include <math.h>
#include <stdint.h>

#define EMBED   1024
#define NHEADS  16
#define HDIM    64
#define BATCH   2
#define SEQ     2048
#define MTOT    (BATCH*SEQ)
#define LOG2E   1.4426950408889634f

// ---------------- scratch (static device globals: allocation-guard legal) ---
// g_Q: [b,h,s,d] natural.  g_K: [b,h,s,d] with d permuted within 8-groups.
// g_V: [b,h,d,s] (transposed).
__device__ float g_Q[(size_t)BATCH*NHEADS*SEQ*HDIM];
__device__ float g_K[(size_t)BATCH*NHEADS*SEQ*HDIM];
__device__ float g_V[(size_t)BATCH*NHEADS*SEQ*HDIM];

// ---------------- helpers ---------------------------------------------------
__device__ __forceinline__ unsigned f2tf(float f) {
    unsigned u;
    asm("cvt.rna.tf32.f32 %0, %1;" : "=r"(u) : "f"(f));
    return u;
}

__device__ __forceinline__ float ex2(float x) {
    float r;
    asm("ex2.approx.f32 %0, %1;" : "=f"(r) : "f"(x));
    return r;
}

// D = A(16x8,row) * B(8x8,col) + D   (tf32 inputs, f32 accum)
__device__ __forceinline__ void mma8(float* c, const unsigned* a, unsigned b0, unsigned b1) {
    asm volatile(
        "mma.sync.aligned.m16n8k8.row.col.f32.tf32.tf32.f32 "
        "{%0,%1,%2,%3},{%4,%5,%6,%7},{%8,%9},{%0,%1,%2,%3};\n"
        : "+f"(c[0]), "+f"(c[1]), "+f"(c[2]), "+f"(c[3])
        : "r"(a[0]), "r"(a[1]), "r"(a[2]), "r"(a[3]), "r"(b0), "r"(b1));
}

__device__ __forceinline__ void cp16(void* smem_dst, const void* gsrc) {
    unsigned s = (unsigned)__cvta_generic_to_shared(smem_dst);
    asm volatile("cp.async.cg.shared.global [%0], [%1], 16;\n" :: "r"(s), "l"(gsrc));
}
__device__ __forceinline__ void cp_commit() { asm volatile("cp.async.commit_group;\n"); }
__device__ __forceinline__ void cp_wait0()  { asm volatile("cp.async.wait_group 0;\n"); }

// robust scalar read: int32 / float32 / float64
__device__ __forceinline__ float load_scale(const void* p) {
    int iv = *(const int*)p;
    if (iv > 0 && iv < (1 << 20)) return (float)iv;
    float f = __int_as_float(iv);
    if (f > 1e-6f && f < 1e6f) return f;
    return (float)(*(const double*)p);
}

// column permutation within 8-groups: natural index i -> stored position
__device__ __forceinline__ int kperm(int i) {   // i in [0,8)
    return ((i & 3) << 1) | (i >> 2);
}

// ---------------- QKV projection GEMM (register double-buffered) -------------
#define BM   128
#define BN   128
#define BKK  32
#define ASTR 36
#define BSTR 136

__global__ void __launch_bounds__(256, 1) qkv_gemm(
    const float* __restrict__ X,
    const float* __restrict__ Wq, const float* __restrict__ bq,
    const float* __restrict__ Wk, const float* __restrict__ bk,
    const float* __restrict__ Wv, const float* __restrict__ bv)
{
    __shared__ unsigned As[BM * ASTR];   // 18.0 KB
    __shared__ unsigned Bs[BKK * BSTR];  // 17.4 KB

    const float* W;
    const float* bias;
    if (blockIdx.z == 0)      { W = Wq; bias = bq; }
    else if (blockIdx.z == 1) { W = Wk; bias = bk; }
    else                      { W = Wv; bias = bv; }

    const int tid  = threadIdx.x;
    const int lane = tid & 31, warp = tid >> 5;
    const int gid  = lane >> 2, tig = lane & 3;
    const int wm   = (warp >> 2) * 64;
    const int wn   = (warp & 3) * 32;
    const int mBase = blockIdx.y * BM;
    const int nBase = blockIdx.x * BN;

    // staging addresses
    const int arow = tid >> 3, acol = (tid & 7) * 4;    // +32 rows per chunk
    const int brow = tid >> 5, bcol = (tid & 31) * 4;   // +8 rows per chunk
    const float* Ag = X + (size_t)(mBase + arow) * EMBED + acol;
    const float* Bg = W + (size_t)brow * EMBED + nBase + bcol;

    float4 ar[4], br[4];
#pragma unroll
    for (int i = 0; i < 4; i++) {
        ar[i] = *(const float4*)(Ag + (size_t)(32 * i) * EMBED);
        br[i] = *(const float4*)(Bg + (size_t)(8 * i) * EMBED);
    }

    float acc[4][4][4];
#pragma unroll
    for (int mt = 0; mt < 4; mt++)
#pragma unroll
        for (int nt = 0; nt < 4; nt++)
#pragma unroll
            for (int j = 0; j < 4; j++) acc[mt][nt][j] = 0.f;

    for (int kk = 0; kk < EMBED; kk += BKK) {
        if (kk) __syncthreads();   // prior tile's frag reads complete
        // cvt + STS.128 current registers
#pragma unroll
        for (int i = 0; i < 4; i++) {
            uint4 u;
            u.x = f2tf(ar[i].x); u.y = f2tf(ar[i].y);
            u.z = f2tf(ar[i].z); u.w = f2tf(ar[i].w);
            *(uint4*)(As + (arow + 32 * i) * ASTR + acol) = u;
            uint4 v;
            v.x = f2tf(br[i].x); v.y = f2tf(br[i].y);
            v.z = f2tf(br[i].z); v.w = f2tf(br[i].w);
            *(uint4*)(Bs + (brow + 8 * i) * BSTR + bcol) = v;
        }
        __syncthreads();

        // prefetch next tile into registers (hidden under mma)
        if (kk + BKK < EMBED) {
            const float* Agn = Ag + kk + BKK;
            const float* Bgn = Bg + (size_t)(kk + BKK) * EMBED;
#pragma unroll
            for (int i = 0; i < 4; i++) {
                ar[i] = *(const float4*)(Agn + (size_t)(32 * i) * EMBED);
                br[i] = *(const float4*)(Bgn + (size_t)(8 * i) * EMBED);
            }
        }

#pragma unroll
        for (int ks = 0; ks < BKK; ks += 8) {
            unsigned a[4][4], bf[4][2];
#pragma unroll
            for (int mt = 0; mt < 4; mt++) {
                int r0 = wm + mt * 16;
                a[mt][0] = As[(r0 + gid)     * ASTR + ks + tig];
                a[mt][1] = As[(r0 + gid + 8) * ASTR + ks + tig];
                a[mt][2] = As[(r0 + gid)     * ASTR + ks + tig + 4];
                a[mt][3] = As[(r0 + gid + 8) * ASTR + ks + tig + 4];
            }
#pragma unroll
            for (int nt = 0; nt < 4; nt++) {
                int c0 = wn + nt * 8;
                bf[nt][0] = Bs[(ks + tig)     * BSTR + c0 + gid];
                bf[nt][1] = Bs[(ks + tig + 4) * BSTR + c0 + gid];
            }
#pragma unroll
            for (int mt = 0; mt < 4; mt++)
#pragma unroll
                for (int nt = 0; nt < 4; nt++)
                    mma8(acc[mt][nt], a[mt], bf[nt][0], bf[nt][1]);
        }
    }

    // epilogue: bias + scatter. Layout depends on which output.
    const int z = blockIdx.z;
#pragma unroll
    for (int nt = 0; nt < 4; nt++) {
        int c0 = nBase + wn + nt * 8 + 2 * tig;       // even
        float b0 = bias[c0], b1 = bias[c0 + 1];
        int h = c0 >> 6;
#pragma unroll
        for (int mt = 0; mt < 4; mt++) {
#pragma unroll
            for (int rr = 0; rr < 2; rr++) {
                int r = mBase + wm + mt * 16 + gid + rr * 8;
                int bi = r >> 11, s = r & (SEQ - 1);
                float v0 = acc[mt][nt][rr * 2 + 0] + b0;
                float v1 = acc[mt][nt][rr * 2 + 1] + b1;
                size_t hb = (size_t)(bi * NHEADS + h);
                if (z == 0) {           // Q: [b,h,s,d] natural
                    float* op = g_Q + (hb * SEQ + s) * HDIM + (c0 & 63);
                    op[0] = v0; op[1] = v1;
                } else if (z == 1) {    // K: [b,h,s,d], d permuted in 8-groups
                    int grp = c0 & 56;  // within-head 8-group base
                    int d0 = grp | kperm(c0 & 7);
                    int d1 = grp | kperm((c0 & 7) + 1);
                    float* op = g_K + (hb * SEQ + s) * HDIM;
                    op[d0] = v0; op[d1] = v1;
                } else {                // V: [b,h,d,s] transposed
                    int d = c0 & 63;
                    float* op = g_V + (hb * HDIM + d) * SEQ + s;
                    op[0] = v0; op[SEQ] = v1;
                }
            }
        }
    }
}

// ---------------- flash attention v3 ------------------------------------------
// 4 warps, BQ=64, warp = 16 rows x 64 cols. K frag pairs adjacent (gmem perm),
// V transposed in gmem -> both K and V fragments load as LDS.64.
#define KW 68        // 68 == 4 mod 32 -> 2-phase conflict-free LDS.64
#define VW 68
#define TILE_WORDS (64*KW)
#define ATTN_SMEM_BYTES (4*TILE_WORDS*4)

__device__ __forceinline__ void stage_kv(const float* Kg, const float* Vg, int kt,
                                         float* Kd, float* Vd, int tid)
{
#pragma unroll
    for (int w = 0; w < 8; w++) {
        int c = tid + w * 128;           // 1024 16B-chunks per tile
        int row = c >> 4, col = (c & 15) * 4;
        cp16(Kd + row * KW + col, Kg + (size_t)(kt + row) * HDIM + col);
        // V transposed: row = dim, col = key
        cp16(Vd + row * VW + col, Vg + (size_t)row * SEQ + kt + col);
    }
}

__global__ void __launch_bounds__(128, 3) attn_kernel(
    const int* __restrict__ maskg, const void* __restrict__ scale_ptr,
    float* __restrict__ out)
{
    extern __shared__ float smem[];
    float* K0 = smem;
    float* V0 = K0 + TILE_WORDS;
    float* K1 = V0 + TILE_WORDS;
    float* V1 = K1 + TILE_WORDS;

    const int tid  = threadIdx.x;
    const int lane = tid & 31, warp = tid >> 5;
    const int gid  = lane >> 2, tig = lane & 3;
    const int wm   = warp * 16;

    const int bh = blockIdx.y;
    const int b  = bh >> 4;
    const int q0 = blockIdx.x * 64;

    const float* Qg = g_Q + (size_t)bh * SEQ * HDIM;
    const float* Kg = g_K + (size_t)bh * SEQ * HDIM;
    const float* Vg = g_V + (size_t)bh * SEQ * HDIM;
    const int* mrow = maskg + b * SEQ;

    const float rscale = 1.0f / load_scale(scale_ptr);

    // ---- stage Q (scaled, tf32, natural cols) into K1 region, lift to regs
    unsigned* Qs = (unsigned*)K1;
#pragma unroll
    for (int w = 0; w < 8; w++) {
        int c = tid + w * 128;
        int row = c >> 4, col = (c & 15) * 4;
        float4 v = *(const float4*)(Qg + (size_t)(q0 + row) * HDIM + col);
        uint4 u;
        u.x = f2tf(v.x * rscale); u.y = f2tf(v.y * rscale);
        u.z = f2tf(v.z * rscale); u.w = f2tf(v.w * rscale);
        *(uint4*)(Qs + row * KW + col) = u;
    }
    __syncthreads();

    unsigned q[8][4];
#pragma unroll
    for (int ks = 0; ks < 8; ks++) {
        q[ks][0] = Qs[(wm + gid)     * KW + 8*ks + tig];
        q[ks][1] = Qs[(wm + gid + 8) * KW + 8*ks + tig];
        q[ks][2] = Qs[(wm + gid)     * KW + 8*ks + tig + 4];
        q[ks][3] = Qs[(wm + gid + 8) * KW + 8*ks + tig + 4];
    }
    __syncthreads();   // done reading Qs before buf1 staged

    stage_kv(Kg, Vg, 0, K0, V0, tid);
    cp_commit();

    float o[8][4];
#pragma unroll
    for (int nt = 0; nt < 8; nt++)
#pragma unroll
        for (int j = 0; j < 4; j++) o[nt][j] = 0.f;
    float m0 = -1e30f, m1 = -1e30f, l0 = 0.f, l1 = 0.f;

    for (int kt = 0; kt < SEQ; kt += 64) {
        cp_wait0();
        __syncthreads();

        int cur = (kt >> 6) & 1;
        if (kt + 64 < SEQ) {
            stage_kv(Kg, Vg, kt + 64, cur ? K0 : K1, cur ? V0 : V1, tid);
            cp_commit();
        }
        const unsigned* Ku = (const unsigned*)(cur ? K1 : K0);
        const unsigned* Vu = (const unsigned*)(cur ? V1 : V0);

        unsigned mb0 = __ballot_sync(0xffffffffu, mrow[kt + lane] != 0);
        unsigned mb1 = __ballot_sync(0xffffffffu, mrow[kt + 32 + lane] != 0);

        // ---- S = Q @ K^T  (16 x 64 per warp); K frag pairs via LDS.64
        float s[8][4];
#pragma unroll
        for (int nt = 0; nt < 8; nt++)
#pragma unroll
            for (int j = 0; j < 4; j++) s[nt][j] = 0.f;

#pragma unroll
        for (int ks = 0; ks < 8; ks++) {
#pragma unroll
            for (int nt = 0; nt < 8; nt++) {
                uint2 bb = *(const uint2*)(Ku + (8*nt + gid) * KW + 8*ks + 2*tig);
                mma8(s[nt], q[ks], bb.x, bb.y);
            }
        }

        // ---- mask
        if ((mb0 & mb1) != 0xffffffffu) {
#pragma unroll
            for (int nt = 0; nt < 8; nt++) {
                int col = 8*nt + 2*tig;
                unsigned mw = (nt < 4) ? mb0 : mb1;
                if (!((mw >> (col & 31)) & 1u))       { s[nt][0] = -1e30f; s[nt][2] = -1e30f; }
                if (!((mw >> ((col + 1) & 31)) & 1u)) { s[nt][1] = -1e30f; s[nt][3] = -1e30f; }
            }
        }

        // ---- row max (quad shuffles)
        float rm0 = s[0][0], rm1 = s[0][2];
#pragma unroll
        for (int nt = 0; nt < 8; nt++) {
            rm0 = fmaxf(rm0, fmaxf(s[nt][0], s[nt][1]));
            rm1 = fmaxf(rm1, fmaxf(s[nt][2], s[nt][3]));
        }
        rm0 = fmaxf(rm0, __shfl_xor_sync(0xffffffffu, rm0, 1));
        rm0 = fmaxf(rm0, __shfl_xor_sync(0xffffffffu, rm0, 2));
        rm1 = fmaxf(rm1, __shfl_xor_sync(0xffffffffu, rm1, 1));
        rm1 = fmaxf(rm1, __shfl_xor_sync(0xffffffffu, rm1, 2));

        float m0n = fmaxf(m0, rm0), m1n = fmaxf(m1, rm1);
        float a0 = ex2((m0 - m0n) * LOG2E);
        float a1 = ex2((m1 - m1n) * LOG2E);
        m0 = m0n; m1 = m1n;

        // ---- p = exp(s - m), row sums
        float ls0 = 0.f, ls1 = 0.f;
#pragma unroll
        for (int nt = 0; nt < 8; nt++) {
            s[nt][0] = ex2((s[nt][0] - m0) * LOG2E);
            s[nt][1] = ex2((s[nt][1] - m0) * LOG2E);
            s[nt][2] = ex2((s[nt][2] - m1) * LOG2E);
            s[nt][3] = ex2((s[nt][3] - m1) * LOG2E);
            ls0 += s[nt][0] + s[nt][1];
            ls1 += s[nt][2] + s[nt][3];
        }
        ls0 += __shfl_xor_sync(0xffffffffu, ls0, 1);
        ls0 += __shfl_xor_sync(0xffffffffu, ls0, 2);
        ls1 += __shfl_xor_sync(0xffffffffu, ls1, 1);
        ls1 += __shfl_xor_sync(0xffffffffu, ls1, 2);
        l0 = l0 * a0 + ls0;
        l1 = l1 * a1 + ls1;

        // ---- rescale O, then O += P @ V (V transposed; LDS.64 pairs)
#pragma unroll
        for (int nt = 0; nt < 8; nt++) {
            o[nt][0] *= a0; o[nt][1] *= a0; o[nt][2] *= a1; o[nt][3] *= a1;
        }
#pragma unroll
        for (int g = 0; g < 8; g++) {
            unsigned a[4];
            a[0] = f2tf(s[g][0]);   // key 8g+2tig     -> mma-k = tig
            a[1] = f2tf(s[g][2]);
            a[2] = f2tf(s[g][1]);   // key 8g+2tig+1   -> mma-k = tig+4
            a[3] = f2tf(s[g][3]);
#pragma unroll
            for (int nt = 0; nt < 8; nt++) {
                uint2 vv = *(const uint2*)(Vu + (8*nt + gid) * VW + 8*g + 2*tig);
                mma8(o[nt], a, vv.x, vv.y);
            }
        }
    }

    // ---- epilogue: O / l
    float i0 = 1.f / l0, i1 = 1.f / l1;
    size_t r0base = ((size_t)bh * SEQ + q0 + wm + gid) * HDIM;
    size_t r1base = r0base + (size_t)8 * HDIM;
#pragma unroll
    for (int nt = 0; nt < 8; nt++) {
        int col = 8*nt + 2*tig;
        float2 v0 = { o[nt][0] * i0, o[nt][1] * i0 };
        float2 v1 = { o[nt][2] * i1, o[nt][3] * i1 };
        *(float2*)(out + r0base + col) = v0;
        *(float2*)(out + r1base + col) = v1;
    }
}

// ---------------- launcher ----------------------------------------------------
extern "C" void kernel_launch(void* const* d_in, const int* in_sizes, int n_in,
                              void* d_out, int out_size)
{
    const float* x    = (const float*)d_in[0];
    const int*   mask = (const int*)d_in[1];
    const void*  scal = d_in[2];
    const float* Wq   = (const float*)d_in[3];
    const float* bq   = (const float*)d_in[4];
    const float* Wk   = (const float*)d_in[5];
    const float* bk   = (const float*)d_in[6];
    const float* Wv   = (const float*)d_in[7];
    const float* bv   = (const float*)d_in[8];
    float* out = (float*)d_out;

    dim3 g1(EMBED / BN, MTOT / BM, 3);
    qkv_gemm<<<g1, 256>>>(x, Wq, bq, Wk, bk, Wv, bv);

    cudaFuncSetAttribute(attn_kernel, cudaFuncAttributeMaxDynamicSharedMemorySize,
                         ATTN_SMEM_BYTES);
    dim3 g2(SEQ / 64, BATCH * NHEADS);
    attn_kernel<<<g2, 128, ATTN_SMEM_BYTES>>>(mask, scal, out);
}

// round 4
// speedup vs baseline: 1.1482x; 1.1482x over previous
#include <cuda_runtime.h>
#include <math.h>
#include <stdint.h>

#define EMBED   1024
#define NHEADS  16
#define HDIM    64
#define BATCH   2
#define SEQ     2048
#define MTOT    (BATCH*SEQ)
#define LOG2E   1.4426950408889634f

// ---------------- scratch (static device globals: allocation-guard legal) ---
// all [b,h,s,d] natural layout
__device__ float g_Q[(size_t)BATCH*NHEADS*SEQ*HDIM];
__device__ float g_K[(size_t)BATCH*NHEADS*SEQ*HDIM];
__device__ float g_V[(size_t)BATCH*NHEADS*SEQ*HDIM];

// ---------------- helpers ---------------------------------------------------
__device__ __forceinline__ unsigned f2tf(float f) {
    unsigned u;
    asm("cvt.rna.tf32.f32 %0, %1;" : "=r"(u) : "f"(f));
    return u;
}

__device__ __forceinline__ float ex2(float x) {
    float r;
    asm("ex2.approx.f32 %0, %1;" : "=f"(r) : "f"(x));
    return r;
}

// D = A(16x8,row) * B(8x8,col) + D   (tf32 inputs, f32 accum)
__device__ __forceinline__ void mma8(float* c, const unsigned* a, unsigned b0, unsigned b1) {
    asm volatile(
        "mma.sync.aligned.m16n8k8.row.col.f32.tf32.tf32.f32 "
        "{%0,%1,%2,%3},{%4,%5,%6,%7},{%8,%9},{%0,%1,%2,%3};\n"
        : "+f"(c[0]), "+f"(c[1]), "+f"(c[2]), "+f"(c[3])
        : "r"(a[0]), "r"(a[1]), "r"(a[2]), "r"(a[3]), "r"(b0), "r"(b1));
}

__device__ __forceinline__ void cp16(void* smem_dst, const void* gsrc) {
    unsigned s = (unsigned)__cvta_generic_to_shared(smem_dst);
    asm volatile("cp.async.cg.shared.global [%0], [%1], 16;\n" :: "r"(s), "l"(gsrc));
}
__device__ __forceinline__ void cp_commit() { asm volatile("cp.async.commit_group;\n"); }
__device__ __forceinline__ void cp_wait0()  { asm volatile("cp.async.wait_group 0;\n"); }

// robust scalar read: int32 / float32 / float64
__device__ __forceinline__ float load_scale(const void* p) {
    int iv = *(const int*)p;
    if (iv > 0 && iv < (1 << 20)) return (float)iv;
    float f = __int_as_float(iv);
    if (f > 1e-6f && f < 1e6f) return f;
    return (float)(*(const double*)p);
}

// ---------------- QKV projection GEMM (register double-buffered) -------------
// Natural-layout coalesced epilogue (round-2 style).
#define BM   128
#define BN   128
#define BKK  32
#define ASTR 36
#define BSTR 136

__global__ void __launch_bounds__(256, 1) qkv_gemm(
    const float* __restrict__ X,
    const float* __restrict__ Wq, const float* __restrict__ bq,
    const float* __restrict__ Wk, const float* __restrict__ bk,
    const float* __restrict__ Wv, const float* __restrict__ bv)
{
    __shared__ unsigned As[BM * ASTR];   // 18.0 KB
    __shared__ unsigned Bs[BKK * BSTR];  // 17.4 KB

    const float* W;
    const float* bias;
    float* Out;
    if (blockIdx.z == 0)      { W = Wq; bias = bq; Out = g_Q; }
    else if (blockIdx.z == 1) { W = Wk; bias = bk; Out = g_K; }
    else                      { W = Wv; bias = bv; Out = g_V; }

    const int tid  = threadIdx.x;
    const int lane = tid & 31, warp = tid >> 5;
    const int gid  = lane >> 2, tig = lane & 3;
    const int wm   = (warp >> 2) * 64;
    const int wn   = (warp & 3) * 32;
    const int mBase = blockIdx.y * BM;
    const int nBase = blockIdx.x * BN;

    // staging addresses
    const int arow = tid >> 3, acol = (tid & 7) * 4;    // A: 32 rows per chunk
    const int brow = tid >> 5, bcol = (tid & 31) * 4;   // B: 8 rows per chunk
    const float* Ag = X + (size_t)(mBase + arow) * EMBED + acol;
    const float* Bg = W + (size_t)brow * EMBED + nBase + bcol;

    float4 ar[4], br[4];
#pragma unroll
    for (int i = 0; i < 4; i++) {
        ar[i] = *(const float4*)(Ag + (size_t)(32 * i) * EMBED);
        br[i] = *(const float4*)(Bg + (size_t)(8 * i) * EMBED);
    }

    float acc[4][4][4];
#pragma unroll
    for (int mt = 0; mt < 4; mt++)
#pragma unroll
        for (int nt = 0; nt < 4; nt++)
#pragma unroll
            for (int j = 0; j < 4; j++) acc[mt][nt][j] = 0.f;

    for (int kk = 0; kk < EMBED; kk += BKK) {
        if (kk) __syncthreads();   // prior tile's fragment reads complete
        // cvt(rna) + STS.128 the staged registers
#pragma unroll
        for (int i = 0; i < 4; i++) {
            uint4 u;
            u.x = f2tf(ar[i].x); u.y = f2tf(ar[i].y);
            u.z = f2tf(ar[i].z); u.w = f2tf(ar[i].w);
            *(uint4*)(As + (arow + 32 * i) * ASTR + acol) = u;
            uint4 v;
            v.x = f2tf(br[i].x); v.y = f2tf(br[i].y);
            v.z = f2tf(br[i].z); v.w = f2tf(br[i].w);
            *(uint4*)(Bs + (brow + 8 * i) * BSTR + bcol) = v;
        }
        __syncthreads();

        // prefetch next k-tile into registers (hidden under the mma below)
        if (kk + BKK < EMBED) {
            const float* Agn = Ag + kk + BKK;
            const float* Bgn = Bg + (size_t)(kk + BKK) * EMBED;
#pragma unroll
            for (int i = 0; i < 4; i++) {
                ar[i] = *(const float4*)(Agn + (size_t)(32 * i) * EMBED);
                br[i] = *(const float4*)(Bgn + (size_t)(8 * i) * EMBED);
            }
        }

#pragma unroll
        for (int ks = 0; ks < BKK; ks += 8) {
            unsigned a[4][4], bf[4][2];
#pragma unroll
            for (int mt = 0; mt < 4; mt++) {
                int r0 = wm + mt * 16;
                a[mt][0] = As[(r0 + gid)     * ASTR + ks + tig];
                a[mt][1] = As[(r0 + gid + 8) * ASTR + ks + tig];
                a[mt][2] = As[(r0 + gid)     * ASTR + ks + tig + 4];
                a[mt][3] = As[(r0 + gid + 8) * ASTR + ks + tig + 4];
            }
#pragma unroll
            for (int nt = 0; nt < 4; nt++) {
                int c0 = wn + nt * 8;
                bf[nt][0] = Bs[(ks + tig)     * BSTR + c0 + gid];
                bf[nt][1] = Bs[(ks + tig + 4) * BSTR + c0 + gid];
            }
#pragma unroll
            for (int mt = 0; mt < 4; mt++)
#pragma unroll
                for (int nt = 0; nt < 4; nt++)
                    mma8(acc[mt][nt], a[mt], bf[nt][0], bf[nt][1]);
        }
    }

    // epilogue: bias + coalesced pair-writes into [b,h,s,d]
#pragma unroll
    for (int nt = 0; nt < 4; nt++) {
        int c0 = nBase + wn + nt * 8 + 2 * tig;
        float b0 = bias[c0], b1 = bias[c0 + 1];
        int h = c0 >> 6, d = c0 & 63;
#pragma unroll
        for (int mt = 0; mt < 4; mt++) {
#pragma unroll
            for (int rr = 0; rr < 2; rr++) {
                int r = mBase + wm + mt * 16 + gid + rr * 8;
                int bi = r >> 11, s = r & (SEQ - 1);
                float* op = Out + (((size_t)(bi * NHEADS + h) * SEQ + s) * HDIM) + d;
                op[0] = acc[mt][nt][rr * 2 + 0] + b0;
                op[1] = acc[mt][nt][rr * 2 + 1] + b1;
            }
        }
    }
}

// ---------------- flash attention (round-2 version, measured 219us) ----------
// 4 warps, BQ=64, each warp: 16 rows x full 64 cols.
// Q frags + softmax state + O in registers. P never touches smem (V row-permuted).
#define KW 68        // K tile stride (conflict-free: 4*gid+tig)
#define VW 72        // V tile stride (conflict-free: 8*tig+gid)
#define TILE_K_WORDS (64*KW)
#define TILE_V_WORDS (64*VW)
#define ATTN_SMEM_BYTES (2*(TILE_K_WORDS + TILE_V_WORDS)*4)

__device__ __forceinline__ void stage_kv(const float* Kg, const float* Vg, int kt,
                                         float* Kd, float* Vd, int tid)
{
#pragma unroll
    for (int w = 0; w < 8; w++) {
        int c = tid + w * 128;           // 1024 chunks of 16B per tile
        int row = c >> 4, col = (c & 15) * 4;
        cp16(Kd + row * KW + col, Kg + (size_t)(kt + row) * HDIM + col);
        // sigma row permutation so S-accum regs serve as P A-frags in P@V
        int pr = (row & ~7) | (((row & 7) >> 1)) | ((row & 1) << 2);
        cp16(Vd + pr * VW + col, Vg + (size_t)(kt + row) * HDIM + col);
    }
}

__global__ void __launch_bounds__(128, 3) attn_kernel(
    const int* __restrict__ maskg, const void* __restrict__ scale_ptr,
    float* __restrict__ out)
{
    extern __shared__ float smem[];
    float* K0 = smem;
    float* V0 = K0 + TILE_K_WORDS;
    float* K1 = V0 + TILE_V_WORDS;
    float* V1 = K1 + TILE_K_WORDS;

    const int tid  = threadIdx.x;
    const int lane = tid & 31, warp = tid >> 5;
    const int gid  = lane >> 2, tig = lane & 3;
    const int wm   = warp * 16;

    const int bh = blockIdx.y;
    const int b  = bh >> 4;
    const int q0 = blockIdx.x * 64;

    const float* Qg = g_Q + (size_t)bh * SEQ * HDIM;
    const float* Kg = g_K + (size_t)bh * SEQ * HDIM;
    const float* Vg = g_V + (size_t)bh * SEQ * HDIM;
    const int* mrow = maskg + b * SEQ;

    const float rscale = 1.0f / load_scale(scale_ptr);

    // ---- stage Q (scaled, tf32) into K1 region, then lift frags to registers
    unsigned* Qs = (unsigned*)K1;
#pragma unroll
    for (int w = 0; w < 8; w++) {
        int c = tid + w * 128;
        int row = c >> 4, col = (c & 15) * 4;
        float4 v = *(const float4*)(Qg + (size_t)(q0 + row) * HDIM + col);
        uint4 u;
        u.x = f2tf(v.x * rscale); u.y = f2tf(v.y * rscale);
        u.z = f2tf(v.z * rscale); u.w = f2tf(v.w * rscale);
        *(uint4*)(Qs + row * KW + col) = u;
    }
    __syncthreads();

    unsigned q[8][4];
#pragma unroll
    for (int ks = 0; ks < 8; ks++) {
        q[ks][0] = Qs[(wm + gid)     * KW + 8*ks + tig];
        q[ks][1] = Qs[(wm + gid + 8) * KW + 8*ks + tig];
        q[ks][2] = Qs[(wm + gid)     * KW + 8*ks + tig + 4];
        q[ks][3] = Qs[(wm + gid + 8) * KW + 8*ks + tig + 4];
    }
    __syncthreads();   // done reading Qs before buf1 staged

    // issue first K/V tile (buf0)
    stage_kv(Kg, Vg, 0, K0, V0, tid);
    cp_commit();

    float o[8][4];
#pragma unroll
    for (int nt = 0; nt < 8; nt++)
#pragma unroll
        for (int j = 0; j < 4; j++) o[nt][j] = 0.f;
    float m0 = -1e30f, m1 = -1e30f, l0 = 0.f, l1 = 0.f;

    for (int kt = 0; kt < SEQ; kt += 64) {
        cp_wait0();
        __syncthreads();      // current tile visible; all done with other buf

        int cur = (kt >> 6) & 1;
        if (kt + 64 < SEQ) {  // prefetch next into the other buffer
            stage_kv(Kg, Vg, kt + 64, cur ? K0 : K1, cur ? V0 : V1, tid);
            cp_commit();
        }
        const unsigned* Ku = (const unsigned*)(cur ? K1 : K0);
        const unsigned* Vu = (const unsigned*)(cur ? V1 : V0);

        unsigned mb0 = __ballot_sync(0xffffffffu, mrow[kt + lane] != 0);
        unsigned mb1 = __ballot_sync(0xffffffffu, mrow[kt + 32 + lane] != 0);

        // ---- S = Q @ K^T  (16 x 64 per warp)
        float s[8][4];
#pragma unroll
        for (int nt = 0; nt < 8; nt++)
#pragma unroll
            for (int j = 0; j < 4; j++) s[nt][j] = 0.f;

#pragma unroll
        for (int ks = 0; ks < 8; ks++) {
#pragma unroll
            for (int nt = 0; nt < 8; nt++) {
                unsigned b0 = Ku[(8*nt + gid) * KW + 8*ks + tig];
                unsigned b1 = Ku[(8*nt + gid) * KW + 8*ks + tig + 4];
                mma8(s[nt], q[ks], b0, b1);
            }
        }

        // ---- mask
        if ((mb0 & mb1) != 0xffffffffu) {
#pragma unroll
            for (int nt = 0; nt < 8; nt++) {
                int col = 8*nt + 2*tig;
                unsigned mw = (nt < 4) ? mb0 : mb1;
                if (!((mw >> (col & 31)) & 1u))       { s[nt][0] = -1e30f; s[nt][2] = -1e30f; }
                if (!((mw >> ((col + 1) & 31)) & 1u)) { s[nt][1] = -1e30f; s[nt][3] = -1e30f; }
            }
        }

        // ---- row max (registers + quad shuffles)
        float rm0 = s[0][0], rm1 = s[0][2];
#pragma unroll
        for (int nt = 0; nt < 8; nt++) {
            rm0 = fmaxf(rm0, fmaxf(s[nt][0], s[nt][1]));
            rm1 = fmaxf(rm1, fmaxf(s[nt][2], s[nt][3]));
        }
        rm0 = fmaxf(rm0, __shfl_xor_sync(0xffffffffu, rm0, 1));
        rm0 = fmaxf(rm0, __shfl_xor_sync(0xffffffffu, rm0, 2));
        rm1 = fmaxf(rm1, __shfl_xor_sync(0xffffffffu, rm1, 1));
        rm1 = fmaxf(rm1, __shfl_xor_sync(0xffffffffu, rm1, 2));

        float m0n = fmaxf(m0, rm0), m1n = fmaxf(m1, rm1);
        float a0 = ex2((m0 - m0n) * LOG2E);
        float a1 = ex2((m1 - m1n) * LOG2E);
        m0 = m0n; m1 = m1n;

        // ---- p = exp(s - m), row sums
        float ls0 = 0.f, ls1 = 0.f;
#pragma unroll
        for (int nt = 0; nt < 8; nt++) {
            s[nt][0] = ex2((s[nt][0] - m0) * LOG2E);
            s[nt][1] = ex2((s[nt][1] - m0) * LOG2E);
            s[nt][2] = ex2((s[nt][2] - m1) * LOG2E);
            s[nt][3] = ex2((s[nt][3] - m1) * LOG2E);
            ls0 += s[nt][0] + s[nt][1];
            ls1 += s[nt][2] + s[nt][3];
        }
        ls0 += __shfl_xor_sync(0xffffffffu, ls0, 1);
        ls0 += __shfl_xor_sync(0xffffffffu, ls0, 2);
        ls1 += __shfl_xor_sync(0xffffffffu, ls1, 1);
        ls1 += __shfl_xor_sync(0xffffffffu, ls1, 2);
        l0 = l0 * a0 + ls0;
        l1 = l1 * a1 + ls1;

        // ---- rescale O, then O += P @ V (P A-frags straight from registers)
#pragma unroll
        for (int nt = 0; nt < 8; nt++) {
            o[nt][0] *= a0; o[nt][1] *= a0; o[nt][2] *= a1; o[nt][3] *= a1;
        }
#pragma unroll
        for (int g = 0; g < 8; g++) {
            unsigned a[4];
            a[0] = f2tf(s[g][0]);   // c0 -> A slot (row, tig)
            a[1] = f2tf(s[g][2]);   // c2 -> A slot (row+8, tig)
            a[2] = f2tf(s[g][1]);   // c1 -> A slot (row, tig+4)
            a[3] = f2tf(s[g][3]);   // c3 -> A slot (row+8, tig+4)
#pragma unroll
            for (int nt = 0; nt < 8; nt++) {
                unsigned b0 = Vu[(8*g + tig)     * VW + 8*nt + gid];
                unsigned b1 = Vu[(8*g + tig + 4) * VW + 8*nt + gid];
                mma8(o[nt], a, b0, b1);
            }
        }
    }

    // ---- epilogue: O / l
    float i0 = 1.f / l0, i1 = 1.f / l1;
    size_t r0base = ((size_t)bh * SEQ + q0 + wm + gid) * HDIM;
    size_t r1base = r0base + (size_t)8 * HDIM;
#pragma unroll
    for (int nt = 0; nt < 8; nt++) {
        int col = 8*nt + 2*tig;
        float2 v0 = { o[nt][0] * i0, o[nt][1] * i0 };
        float2 v1 = { o[nt][2] * i1, o[nt][3] * i1 };
        *(float2*)(out + r0base + col) = v0;
        *(float2*)(out + r1base + col) = v1;
    }
}

// ---------------- launcher ----------------------------------------------------
extern "C" void kernel_launch(void* const* d_in, const int* in_sizes, int n_in,
                              void* d_out, int out_size)
{
    const float* x    = (const float*)d_in[0];
    const int*   mask = (const int*)d_in[1];
    const void*  scal = d_in[2];
    const float* Wq   = (const float*)d_in[3];
    const float* bq   = (const float*)d_in[4];
    const float* Wk   = (const float*)d_in[5];
    const float* bk   = (const float*)d_in[6];
    const float* Wv   = (const float*)d_in[7];
    const float* bv   = (const float*)d_in[8];
    float* out = (float*)d_out;

    dim3 g1(EMBED / BN, MTOT / BM, 3);
    qkv_gemm<<<g1, 256>>>(x, Wq, bq, Wk, bk, Wv, bv);

    cudaFuncSetAttribute(attn_kernel, cudaFuncAttributeMaxDynamicSharedMemorySize,
                         ATTN_SMEM_BYTES);
    dim3 g2(SEQ / 64, BATCH * NHEADS);
    attn_kernel<<<g2, 128, ATTN_SMEM_BYTES>>>(mask, scal, out);
}

// round 5
// speedup vs baseline: 1.2140x; 1.0573x over previous
#include <cuda_runtime.h>
#include <math.h>
#include <stdint.h>

#define EMBED   1024
#define NHEADS  16
#define HDIM    64
#define BATCH   2
#define SEQ     2048
#define MTOT    (BATCH*SEQ)
#define LOG2E   1.4426950408889634f

// ---------------- scratch (static device globals: allocation-guard legal) ---
__device__ float g_Q[(size_t)BATCH*NHEADS*SEQ*HDIM];
__device__ float g_K[(size_t)BATCH*NHEADS*SEQ*HDIM];
__device__ float g_V[(size_t)BATCH*NHEADS*SEQ*HDIM];
__device__ float g_Xt[(size_t)MTOT*EMBED];          // tf32-rounded X
__device__ float g_Wt[3][(size_t)EMBED*EMBED];      // tf32-rounded Wq/Wk/Wv

// ---------------- helpers ---------------------------------------------------
__device__ __forceinline__ unsigned f2tf(float f) {
    unsigned u;
    asm("cvt.rna.tf32.f32 %0, %1;" : "=r"(u) : "f"(f));
    return u;
}

__device__ __forceinline__ float ex2(float x) {
    float r;
    asm("ex2.approx.f32 %0, %1;" : "=f"(r) : "f"(x));
    return r;
}

// D = A(16x8,row) * B(8x8,col) + D   (tf32 inputs, f32 accum)
__device__ __forceinline__ void mma8(float* c, const unsigned* a, unsigned b0, unsigned b1) {
    asm volatile(
        "mma.sync.aligned.m16n8k8.row.col.f32.tf32.tf32.f32 "
        "{%0,%1,%2,%3},{%4,%5,%6,%7},{%8,%9},{%0,%1,%2,%3};\n"
        : "+f"(c[0]), "+f"(c[1]), "+f"(c[2]), "+f"(c[3])
        : "r"(a[0]), "r"(a[1]), "r"(a[2]), "r"(a[3]), "r"(b0), "r"(b1));
}

__device__ __forceinline__ void cp16(void* smem_dst, const void* gsrc) {
    unsigned s = (unsigned)__cvta_generic_to_shared(smem_dst);
    asm volatile("cp.async.cg.shared.global [%0], [%1], 16;\n" :: "r"(s), "l"(gsrc));
}
__device__ __forceinline__ void cp_commit() { asm volatile("cp.async.commit_group;\n"); }
__device__ __forceinline__ void cp_wait0()  { asm volatile("cp.async.wait_group 0;\n"); }

// robust scalar read: int32 / float32 / float64
__device__ __forceinline__ float load_scale(const void* p) {
    int iv = *(const int*)p;
    if (iv > 0 && iv < (1 << 20)) return (float)iv;
    float f = __int_as_float(iv);
    if (f > 1e-6f && f < 1e6f) return f;
    return (float)(*(const double*)p);
}

// ---------------- tf32 pre-convert pass --------------------------------------
__global__ void __launch_bounds__(256) tf32_convert(
    const float* __restrict__ X,
    const float* __restrict__ Wq, const float* __restrict__ Wk,
    const float* __restrict__ Wv)
{
    const float* src;
    float* dst;
    size_t n4;
    int z = blockIdx.y;
    if (z == 0)      { src = X;  dst = g_Xt;    n4 = (size_t)MTOT * EMBED / 4; }
    else if (z == 1) { src = Wq; dst = g_Wt[0]; n4 = (size_t)EMBED * EMBED / 4; }
    else if (z == 2) { src = Wk; dst = g_Wt[1]; n4 = (size_t)EMBED * EMBED / 4; }
    else             { src = Wv; dst = g_Wt[2]; n4 = (size_t)EMBED * EMBED / 4; }

    size_t stride = (size_t)gridDim.x * blockDim.x;
    for (size_t i = (size_t)blockIdx.x * blockDim.x + threadIdx.x; i < n4; i += stride) {
        float4 v = ((const float4*)src)[i];
        uint4 u;
        u.x = f2tf(v.x); u.y = f2tf(v.y); u.z = f2tf(v.z); u.w = f2tf(v.w);
        ((uint4*)dst)[i] = u;
    }
}

// ---------------- QKV projection GEMM (cp.async double-buffered) -------------
// Inputs are pre-rounded to tf32 bits -> no cvt, no staging regs in mainloop.
#define BM   128
#define BN   128
#define BKK  32
#define ASTR 36
#define BSTR 136
#define A_TILE_WORDS (BM * ASTR)    // 4608
#define B_TILE_WORDS (BKK * BSTR)   // 4352
#define QKV_SMEM_BYTES (2 * (A_TILE_WORDS + B_TILE_WORDS) * 4)   // 71680

__device__ __forceinline__ void qkv_stage(const float* Ab, const float* Bb,
                                          unsigned* Asd, unsigned* Bsd, int tid)
{
#pragma unroll
    for (int i = 0; i < 4; i++) {
        int c = tid + i * 256;                 // 1024 chunks per tile
        int ar = c >> 3, ac = (c & 7) * 4;     // A: 128 rows x 32 cols
        cp16(Asd + ar * ASTR + ac, Ab + (size_t)ar * EMBED + ac);
        int br = c >> 5, bc = (c & 31) * 4;    // B: 32 rows x 128 cols
        cp16(Bsd + br * BSTR + bc, Bb + (size_t)br * EMBED + bc);
    }
}

__global__ void __launch_bounds__(256, 2) qkv_gemm(
    const float* __restrict__ bq, const float* __restrict__ bk,
    const float* __restrict__ bv)
{
    extern __shared__ unsigned qsmem[];
    unsigned* As[2] = { qsmem, qsmem + A_TILE_WORDS };
    unsigned* Bs[2] = { qsmem + 2 * A_TILE_WORDS, qsmem + 2 * A_TILE_WORDS + B_TILE_WORDS };

    const int z = blockIdx.z;
    const float* W = g_Wt[z];
    const float* bias = (z == 0) ? bq : (z == 1) ? bk : bv;
    float* Out = (z == 0) ? g_Q : (z == 1) ? g_K : g_V;

    const int tid  = threadIdx.x;
    const int lane = tid & 31, warp = tid >> 5;
    const int gid  = lane >> 2, tig = lane & 3;
    const int wm   = (warp >> 2) * 64;
    const int wn   = (warp & 3) * 32;
    const int mBase = blockIdx.y * BM;
    const int nBase = blockIdx.x * BN;

    const float* Ag = g_Xt + (size_t)mBase * EMBED;       // + kk
    const float* Bg = W + nBase;                          // + kk*EMBED

    float acc[4][4][4];
#pragma unroll
    for (int mt = 0; mt < 4; mt++)
#pragma unroll
        for (int nt = 0; nt < 4; nt++)
#pragma unroll
            for (int j = 0; j < 4; j++) acc[mt][nt][j] = 0.f;

    qkv_stage(Ag, Bg, As[0], Bs[0], tid);
    cp_commit();

    for (int kk = 0; kk < EMBED; kk += BKK) {
        cp_wait0();
        __syncthreads();

        int cur = (kk >> 5) & 1;
        if (kk + BKK < EMBED) {
            qkv_stage(Ag + kk + BKK, Bg + (size_t)(kk + BKK) * EMBED,
                      As[cur ^ 1], Bs[cur ^ 1], tid);
            cp_commit();
        }
        const unsigned* Ac = As[cur];
        const unsigned* Bc = Bs[cur];

#pragma unroll
        for (int ks = 0; ks < BKK; ks += 8) {
            unsigned a[4][4], bf[4][2];
#pragma unroll
            for (int mt = 0; mt < 4; mt++) {
                int r0 = wm + mt * 16;
                a[mt][0] = Ac[(r0 + gid)     * ASTR + ks + tig];
                a[mt][1] = Ac[(r0 + gid + 8) * ASTR + ks + tig];
                a[mt][2] = Ac[(r0 + gid)     * ASTR + ks + tig + 4];
                a[mt][3] = Ac[(r0 + gid + 8) * ASTR + ks + tig + 4];
            }
#pragma unroll
            for (int nt = 0; nt < 4; nt++) {
                int c0 = wn + nt * 8;
                bf[nt][0] = Bc[(ks + tig)     * BSTR + c0 + gid];
                bf[nt][1] = Bc[(ks + tig + 4) * BSTR + c0 + gid];
            }
#pragma unroll
            for (int mt = 0; mt < 4; mt++)
#pragma unroll
                for (int nt = 0; nt < 4; nt++)
                    mma8(acc[mt][nt], a[mt], bf[nt][0], bf[nt][1]);
        }
    }

    // epilogue: bias + coalesced pair-writes into [b,h,s,d]
#pragma unroll
    for (int nt = 0; nt < 4; nt++) {
        int c0 = nBase + wn + nt * 8 + 2 * tig;
        float b0 = bias[c0], b1 = bias[c0 + 1];
        int h = c0 >> 6, d = c0 & 63;
#pragma unroll
        for (int mt = 0; mt < 4; mt++) {
#pragma unroll
            for (int rr = 0; rr < 2; rr++) {
                int r = mBase + wm + mt * 16 + gid + rr * 8;
                int bi = r >> 11, s = r & (SEQ - 1);
                float* op = Out + (((size_t)(bi * NHEADS + h) * SEQ + s) * HDIM) + d;
                op[0] = acc[mt][nt][rr * 2 + 0] + b0;
                op[1] = acc[mt][nt][rr * 2 + 1] + b1;
            }
        }
    }
}

// ---------------- flash attention (round-2 version, measured ~218us) ---------
// 4 warps, BQ=64, each warp: 16 rows x full 64 cols.
// Q frags + softmax state + O in registers. P never touches smem (V row-permuted).
#define KW 68        // K tile stride (conflict-free: 4*gid+tig)
#define VW 72        // V tile stride (conflict-free: 8*tig+gid)
#define TILE_K_WORDS (64*KW)
#define TILE_V_WORDS (64*VW)
#define ATTN_SMEM_BYTES (2*(TILE_K_WORDS + TILE_V_WORDS)*4)

__device__ __forceinline__ void stage_kv(const float* Kg, const float* Vg, int kt,
                                         float* Kd, float* Vd, int tid)
{
#pragma unroll
    for (int w = 0; w < 8; w++) {
        int c = tid + w * 128;           // 1024 chunks of 16B per tile
        int row = c >> 4, col = (c & 15) * 4;
        cp16(Kd + row * KW + col, Kg + (size_t)(kt + row) * HDIM + col);
        // sigma row permutation so S-accum regs serve as P A-frags in P@V
        int pr = (row & ~7) | (((row & 7) >> 1)) | ((row & 1) << 2);
        cp16(Vd + pr * VW + col, Vg + (size_t)(kt + row) * HDIM + col);
    }
}

__global__ void __launch_bounds__(128, 3) attn_kernel(
    const int* __restrict__ maskg, const void* __restrict__ scale_ptr,
    float* __restrict__ out)
{
    extern __shared__ float smem[];
    float* K0 = smem;
    float* V0 = K0 + TILE_K_WORDS;
    float* K1 = V0 + TILE_V_WORDS;
    float* V1 = K1 + TILE_K_WORDS;

    const int tid  = threadIdx.x;
    const int lane = tid & 31, warp = tid >> 5;
    const int gid  = lane >> 2, tig = lane & 3;
    const int wm   = warp * 16;

    const int bh = blockIdx.y;
    const int b  = bh >> 4;
    const int q0 = blockIdx.x * 64;

    const float* Qg = g_Q + (size_t)bh * SEQ * HDIM;
    const float* Kg = g_K + (size_t)bh * SEQ * HDIM;
    const float* Vg = g_V + (size_t)bh * SEQ * HDIM;
    const int* mrow = maskg + b * SEQ;

    const float rscale = 1.0f / load_scale(scale_ptr);

    // ---- stage Q (scaled, tf32) into K1 region, then lift frags to registers
    unsigned* Qs = (unsigned*)K1;
#pragma unroll
    for (int w = 0; w < 8; w++) {
        int c = tid + w * 128;
        int row = c >> 4, col = (c & 15) * 4;
        float4 v = *(const float4*)(Qg + (size_t)(q0 + row) * HDIM + col);
        uint4 u;
        u.x = f2tf(v.x * rscale); u.y = f2tf(v.y * rscale);
        u.z = f2tf(v.z * rscale); u.w = f2tf(v.w * rscale);
        *(uint4*)(Qs + row * KW + col) = u;
    }
    __syncthreads();

    unsigned q[8][4];
#pragma unroll
    for (int ks = 0; ks < 8; ks++) {
        q[ks][0] = Qs[(wm + gid)     * KW + 8*ks + tig];
        q[ks][1] = Qs[(wm + gid + 8) * KW + 8*ks + tig];
        q[ks][2] = Qs[(wm + gid)     * KW + 8*ks + tig + 4];
        q[ks][3] = Qs[(wm + gid + 8) * KW + 8*ks + tig + 4];
    }
    __syncthreads();   // done reading Qs before buf1 staged

    // issue first K/V tile (buf0)
    stage_kv(Kg, Vg, 0, K0, V0, tid);
    cp_commit();

    float o[8][4];
#pragma unroll
    for (int nt = 0; nt < 8; nt++)
#pragma unroll
        for (int j = 0; j < 4; j++) o[nt][j] = 0.f;
    float m0 = -1e30f, m1 = -1e30f, l0 = 0.f, l1 = 0.f;

    for (int kt = 0; kt < SEQ; kt += 64) {
        cp_wait0();
        __syncthreads();      // current tile visible; all done with other buf

        int cur = (kt >> 6) & 1;
        if (kt + 64 < SEQ) {  // prefetch next into the other buffer
            stage_kv(Kg, Vg, kt + 64, cur ? K0 : K1, cur ? V0 : V1, tid);
            cp_commit();
        }
        const unsigned* Ku = (const unsigned*)(cur ? K1 : K0);
        const unsigned* Vu = (const unsigned*)(cur ? V1 : V0);

        unsigned mb0 = __ballot_sync(0xffffffffu, mrow[kt + lane] != 0);
        unsigned mb1 = __ballot_sync(0xffffffffu, mrow[kt + 32 + lane] != 0);

        // ---- S = Q @ K^T  (16 x 64 per warp)
        float s[8][4];
#pragma unroll
        for (int nt = 0; nt < 8; nt++)
#pragma unroll
            for (int j = 0; j < 4; j++) s[nt][j] = 0.f;

#pragma unroll
        for (int ks = 0; ks < 8; ks++) {
#pragma unroll
            for (int nt = 0; nt < 8; nt++) {
                unsigned b0 = Ku[(8*nt + gid) * KW + 8*ks + tig];
                unsigned b1 = Ku[(8*nt + gid) * KW + 8*ks + tig + 4];
                mma8(s[nt], q[ks], b0, b1);
            }
        }

        // ---- mask
        if ((mb0 & mb1) != 0xffffffffu) {
#pragma unroll
            for (int nt = 0; nt < 8; nt++) {
                int col = 8*nt + 2*tig;
                unsigned mw = (nt < 4) ? mb0 : mb1;
                if (!((mw >> (col & 31)) & 1u))       { s[nt][0] = -1e30f; s[nt][2] = -1e30f; }
                if (!((mw >> ((col + 1) & 31)) & 1u)) { s[nt][1] = -1e30f; s[nt][3] = -1e30f; }
            }
        }

        // ---- row max (registers + quad shuffles)
        float rm0 = s[0][0], rm1 = s[0][2];
#pragma unroll
        for (int nt = 0; nt < 8; nt++) {
            rm0 = fmaxf(rm0, fmaxf(s[nt][0], s[nt][1]));
            rm1 = fmaxf(rm1, fmaxf(s[nt][2], s[nt][3]));
        }
        rm0 = fmaxf(rm0, __shfl_xor_sync(0xffffffffu, rm0, 1));
        rm0 = fmaxf(rm0, __shfl_xor_sync(0xffffffffu, rm0, 2));
        rm1 = fmaxf(rm1, __shfl_xor_sync(0xffffffffu, rm1, 1));
        rm1 = fmaxf(rm1, __shfl_xor_sync(0xffffffffu, rm1, 2));

        float m0n = fmaxf(m0, rm0), m1n = fmaxf(m1, rm1);
        float a0 = ex2((m0 - m0n) * LOG2E);
        float a1 = ex2((m1 - m1n) * LOG2E);
        m0 = m0n; m1 = m1n;

        // ---- p = exp(s - m), row sums
        float ls0 = 0.f, ls1 = 0.f;
#pragma unroll
        for (int nt = 0; nt < 8; nt++) {
            s[nt][0] = ex2((s[nt][0] - m0) * LOG2E);
            s[nt][1] = ex2((s[nt][1] - m0) * LOG2E);
            s[nt][2] = ex2((s[nt][2] - m1) * LOG2E);
            s[nt][3] = ex2((s[nt][3] - m1) * LOG2E);
            ls0 += s[nt][0] + s[nt][1];
            ls1 += s[nt][2] + s[nt][3];
        }
        ls0 += __shfl_xor_sync(0xffffffffu, ls0, 1);
        ls0 += __shfl_xor_sync(0xffffffffu, ls0, 2);
        ls1 += __shfl_xor_sync(0xffffffffu, ls1, 1);
        ls1 += __shfl_xor_sync(0xffffffffu, ls1, 2);
        l0 = l0 * a0 + ls0;
        l1 = l1 * a1 + ls1;

        // ---- rescale O, then O += P @ V (P A-frags straight from registers)
#pragma unroll
        for (int nt = 0; nt < 8; nt++) {
            o[nt][0] *= a0; o[nt][1] *= a0; o[nt][2] *= a1; o[nt][3] *= a1;
        }
#pragma unroll
        for (int g = 0; g < 8; g++) {
            unsigned a[4];
            a[0] = f2tf(s[g][0]);   // c0 -> A slot (row, tig)
            a[1] = f2tf(s[g][2]);   // c2 -> A slot (row+8, tig)
            a[2] = f2tf(s[g][1]);   // c1 -> A slot (row, tig+4)
            a[3] = f2tf(s[g][3]);   // c3 -> A slot (row+8, tig+4)
#pragma unroll
            for (int nt = 0; nt < 8; nt++) {
                unsigned b0 = Vu[(8*g + tig)     * VW + 8*nt + gid];
                unsigned b1 = Vu[(8*g + tig + 4) * VW + 8*nt + gid];
                mma8(o[nt], a, b0, b1);
            }
        }
    }

    // ---- epilogue: O / l
    float i0 = 1.f / l0, i1 = 1.f / l1;
    size_t r0base = ((size_t)bh * SEQ + q0 + wm + gid) * HDIM;
    size_t r1base = r0base + (size_t)8 * HDIM;
#pragma unroll
    for (int nt = 0; nt < 8; nt++) {
        int col = 8*nt + 2*tig;
        float2 v0 = { o[nt][0] * i0, o[nt][1] * i0 };
        float2 v1 = { o[nt][2] * i1, o[nt][3] * i1 };
        *(float2*)(out + r0base + col) = v0;
        *(float2*)(out + r1base + col) = v1;
    }
}

// ---------------- launcher ----------------------------------------------------
extern "C" void kernel_launch(void* const* d_in, const int* in_sizes, int n_in,
                              void* d_out, int out_size)
{
    const float* x    = (const float*)d_in[0];
    const int*   mask = (const int*)d_in[1];
    const void*  scal = d_in[2];
    const float* Wq   = (const float*)d_in[3];
    const float* bq   = (const float*)d_in[4];
    const float* Wk   = (const float*)d_in[5];
    const float* bk   = (const float*)d_in[6];
    const float* Wv   = (const float*)d_in[7];
    const float* bv   = (const float*)d_in[8];
    float* out = (float*)d_out;

    dim3 gc(512, 4);
    tf32_convert<<<gc, 256>>>(x, Wq, Wk, Wv);

    cudaFuncSetAttribute(qkv_gemm, cudaFuncAttributeMaxDynamicSharedMemorySize,
                         QKV_SMEM_BYTES);
    dim3 g1(EMBED / BN, MTOT / BM, 3);
    qkv_gemm<<<g1, 256, QKV_SMEM_BYTES>>>(bq, bk, bv);

    cudaFuncSetAttribute(attn_kernel, cudaFuncAttributeMaxDynamicSharedMemorySize,
                         ATTN_SMEM_BYTES);
    dim3 g2(SEQ / 64, BATCH * NHEADS);
    attn_kernel<<<g2, 128, ATTN_SMEM_BYTES>>>(mask, scal, out);
}